// round 2
// baseline (speedup 1.0000x reference)
#include <cuda_runtime.h>

#define BB 16
#define LL 1024
#define FF 512
#define HH 8
#define DD 64

__device__ float g_q[BB*HH*LL*DD];
__device__ float g_k[BB*HH*LL*DD];
__device__ float g_v[BB*HH*LL*DD];
__device__ float g_x[BB*LL*HH*DD];

// ---------------------------------------------------------------------------
// SGEMM: C = A(M,K) @ W(K,N) + bias, double-buffered smem, BK=8, 128x128 tile,
// 256 threads, 8x8 per-thread microtile.
// mode 0: row-major out; mode 1: scatter to (B,H,L,D)
// ---------------------------------------------------------------------------
__global__ void __launch_bounds__(256) gemm_kernel(
    const float* __restrict__ A, const float* __restrict__ W,
    const float* __restrict__ bias, float* __restrict__ C,
    int M, int N, int K, int mode)
{
    __shared__ float As[2][8][128];
    __shared__ float Bs[2][8][128];

    const int t  = threadIdx.x;
    const int bm = blockIdx.y * 128;
    const int bn = blockIdx.x * 128;
    const int tm = (t >> 4) * 8;
    const int tn = (t & 15) * 8;

    const int ar = t >> 1;
    const int ac = (t & 1) * 4;
    const int wr = t >> 5;
    const int wc = (t & 31) * 4;

    const float* Ap = A + (size_t)(bm + ar) * K + ac;
    const float* Wp = W + (size_t)wr * N + bn + wc;

    float acc[8][8];
    #pragma unroll
    for (int i = 0; i < 8; i++)
        #pragma unroll
        for (int j = 0; j < 8; j++) acc[i][j] = 0.f;

    const int steps = K >> 3;
    float4 av = *(const float4*)Ap; Ap += 8;
    float4 wv = *(const float4*)Wp; Wp += (size_t)8 * N;

    int p = 0;
    for (int s = 0; s < steps; s++) {
        As[p][ac + 0][ar] = av.x;
        As[p][ac + 1][ar] = av.y;
        As[p][ac + 2][ar] = av.z;
        As[p][ac + 3][ar] = av.w;
        *(float4*)&Bs[p][wr][wc] = wv;
        __syncthreads();

        if (s + 1 < steps) {
            av = *(const float4*)Ap; Ap += 8;
            wv = *(const float4*)Wp; Wp += (size_t)8 * N;
        }

        #pragma unroll
        for (int kk = 0; kk < 8; kk++) {
            float a[8], b[8];
            *(float4*)(a    ) = *(const float4*)&As[p][kk][tm];
            *(float4*)(a + 4) = *(const float4*)&As[p][kk][tm + 4];
            *(float4*)(b    ) = *(const float4*)&Bs[p][kk][tn];
            *(float4*)(b + 4) = *(const float4*)&Bs[p][kk][tn + 4];
            #pragma unroll
            for (int i = 0; i < 8; i++)
                #pragma unroll
                for (int j = 0; j < 8; j++)
                    acc[i][j] += a[i] * b[j];
        }
        p ^= 1;
    }

    if (mode == 0) {
        #pragma unroll
        for (int i = 0; i < 8; i++) {
            int gm = bm + tm + i;
            float* cp = C + (size_t)gm * N + bn + tn;
            #pragma unroll
            for (int j = 0; j < 8; j++)
                cp[j] = acc[i][j] + bias[bn + tn + j];
        }
    } else {
        #pragma unroll
        for (int i = 0; i < 8; i++) {
            int gm = bm + tm + i;
            int b_ = gm >> 10;
            int l_ = gm & 1023;
            #pragma unroll
            for (int j = 0; j < 8; j++) {
                int gn = bn + tn + j;
                int h_ = gn >> 6;
                int d_ = gn & 63;
                C[(((size_t)(b_ * HH + h_)) * LL + l_) * DD + d_] = acc[i][j] + bias[gn];
            }
        }
    }
}

// ---------------------------------------------------------------------------
// Flash attention, float4 + XOR-swizzled smem (no pad, no transpose).
// Tile [64][64] floats; logical float4-column c stored at c ^ ((row>>2)&15).
// One CTA per (q-tile 64, h, b). 256 thr = 16x16, 4x4 per-thread S tile.
// ---------------------------------------------------------------------------
__device__ __forceinline__ int swz(int row, int c) {
    // float index of float4-chunk c of row `row`
    return (row << 6) + ((c ^ (row >> 2)) << 2);
}

__global__ void __launch_bounds__(256) attn_kernel(
    const float* __restrict__ q, const float* __restrict__ k,
    const float* __restrict__ v, const float* __restrict__ toep,
    float* __restrict__ x)
{
    extern __shared__ float sm[];
    float* Qs = sm;                // [64][64] swizzled
    float* Ks = Qs + 4096;         // [64][64] swizzled (row-major: key, d)
    float* Vs = Ks + 4096;         // [64][64] swizzled (key, d)
    float* Ps = Vs + 4096;         // [64][64] swizzled (qrow, key)
    float* Tp = Ps + 4096;         // [4096] toeplitz row for head h

    const int t  = threadIdx.x;
    const int qt = blockIdx.x;
    const int h  = blockIdx.y;
    const int b  = blockIdx.z;
    const int bh = b * HH + h;

    const float* qb = q + (size_t)bh * LL * DD + (size_t)qt * 64 * DD;
    const float* kb = k + (size_t)bh * LL * DD;
    const float* vb = v + (size_t)bh * LL * DD;

    // Load Q tile (swizzled) + toeplitz row (flat)
    {
        const float4* qg = (const float4*)qb;
        const float4* tg = (const float4*)(toep + (size_t)h * 4096);
        #pragma unroll
        for (int ch = 0; ch < 4; ch++) {
            int fi = ch * 256 + t;          // float4 index 0..1023
            int row = fi >> 4;
            int c   = fi & 15;
            *(float4*)&Qs[swz(row, c)] = qg[fi];
            *(float4*)&Tp[fi * 4] = tg[fi];
        }
    }

    const int ty = t >> 4;
    const int tx = t & 15;

    float m_[4], l_[4], o[4][4];
    #pragma unroll
    for (int i = 0; i < 4; i++) {
        m_[i] = -1e30f; l_[i] = 0.f;
        #pragma unroll
        for (int c = 0; c < 4; c++) o[i][c] = 0.f;
    }

    int qxi[4], qyi[4];
    #pragma unroll
    for (int i = 0; i < 4; i++) {
        int qr = qt * 64 + ty * 4 + i;
        qxi[i] = qr >> 5;
        qyi[i] = qr & 31;
    }

    const float scale = 0.125f;

    for (int kt = 0; kt < 16; kt++) {
        const float4* kg = (const float4*)(kb + (size_t)kt * 64 * DD);
        const float4* vg = (const float4*)(vb + (size_t)kt * 64 * DD);
        #pragma unroll
        for (int ch = 0; ch < 4; ch++) {
            int fi = ch * 256 + t;
            int row = fi >> 4;
            int c   = fi & 15;
            *(float4*)&Ks[swz(row, c)] = kg[fi];
            *(float4*)&Vs[swz(row, c)] = vg[fi];
        }
        __syncthreads();

        // S = Q @ K^T : both tiles row-major over d, float4 chunks
        float s4[4][4];
        #pragma unroll
        for (int i = 0; i < 4; i++)
            #pragma unroll
            for (int j = 0; j < 4; j++) s4[i][j] = 0.f;

        #pragma unroll 4
        for (int c = 0; c < 16; c++) {
            float4 a[4], bb[4];
            #pragma unroll
            for (int i = 0; i < 4; i++)
                a[i] = *(const float4*)&Qs[swz(ty * 4 + i, c)];
            #pragma unroll
            for (int j = 0; j < 4; j++)
                bb[j] = *(const float4*)&Ks[swz(tx * 4 + j, c)];
            #pragma unroll
            for (int i = 0; i < 4; i++)
                #pragma unroll
                for (int j = 0; j < 4; j++)
                    s4[i][j] += a[i].x * bb[j].x + a[i].y * bb[j].y
                              + a[i].z * bb[j].z + a[i].w * bb[j].w;
        }

        // scale + toeplitz bias
        #pragma unroll
        for (int i = 0; i < 4; i++) {
            #pragma unroll
            for (int j = 0; j < 4; j++) {
                int kc = kt * 64 + tx * 4 + j;
                int dx = qxi[i] - (kc >> 5) + 32;
                int dy = qyi[i] - (kc & 31) + 32;
                s4[i][j] = s4[i][j] * scale + Tp[dx * 64 + dy];
            }
        }

        // online softmax across the 16 tx lanes
        #pragma unroll
        for (int i = 0; i < 4; i++) {
            float tmax = fmaxf(fmaxf(s4[i][0], s4[i][1]), fmaxf(s4[i][2], s4[i][3]));
            #pragma unroll
            for (int off = 8; off >= 1; off >>= 1)
                tmax = fmaxf(tmax, __shfl_xor_sync(0xffffffffu, tmax, off));
            float nm = fmaxf(m_[i], tmax);
            float al = __expf(m_[i] - nm);
            float ts = 0.f;
            #pragma unroll
            for (int j = 0; j < 4; j++) {
                s4[i][j] = __expf(s4[i][j] - nm);
                ts += s4[i][j];
            }
            #pragma unroll
            for (int off = 8; off >= 1; off >>= 1)
                ts += __shfl_xor_sync(0xffffffffu, ts, off);
            l_[i] = l_[i] * al + ts;
            m_[i] = nm;
            #pragma unroll
            for (int c = 0; c < 4; c++) o[i][c] *= al;
            float4 pv = make_float4(s4[i][0], s4[i][1], s4[i][2], s4[i][3]);
            *(float4*)&Ps[swz(ty * 4 + i, tx)] = pv;
        }
        __syncthreads();

        // O += P @ V : chunk over keys (4 at a time)
        #pragma unroll 4
        for (int c = 0; c < 16; c++) {
            float4 a[4], bb[4];
            #pragma unroll
            for (int i = 0; i < 4; i++)
                a[i] = *(const float4*)&Ps[swz(ty * 4 + i, c)];
            #pragma unroll
            for (int jj = 0; jj < 4; jj++)
                bb[jj] = *(const float4*)&Vs[swz(c * 4 + jj, tx)];
            #pragma unroll
            for (int i = 0; i < 4; i++) {
                o[i][0] += a[i].x * bb[0].x + a[i].y * bb[1].x + a[i].z * bb[2].x + a[i].w * bb[3].x;
                o[i][1] += a[i].x * bb[0].y + a[i].y * bb[1].y + a[i].z * bb[2].y + a[i].w * bb[3].y;
                o[i][2] += a[i].x * bb[0].z + a[i].y * bb[1].z + a[i].z * bb[2].z + a[i].w * bb[3].z;
                o[i][3] += a[i].x * bb[0].w + a[i].y * bb[1].w + a[i].z * bb[2].w + a[i].w * bb[3].w;
            }
        }
        __syncthreads();
    }

    // write x in (B, L, H*D) layout
    #pragma unroll
    for (int i = 0; i < 4; i++) {
        float inv = 1.0f / l_[i];
        int qrow = qt * 64 + ty * 4 + i;
        float4 val;
        val.x = o[i][0] * inv; val.y = o[i][1] * inv;
        val.z = o[i][2] * inv; val.w = o[i][3] * inv;
        *(float4*)&x[((size_t)(b * LL + qrow)) * (HH * DD) + h * DD + tx * 4] = val;
    }
}

// ---------------------------------------------------------------------------
extern "C" void kernel_launch(void* const* d_in, const int* in_sizes, int n_in,
                              void* d_out, int out_size)
{
    const float* inq  = (const float*)d_in[0];
    const float* inkv = (const float*)d_in[1];
    const float* Wq   = (const float*)d_in[2];
    const float* bq   = (const float*)d_in[3];
    const float* Wk   = (const float*)d_in[4];
    const float* bk   = (const float*)d_in[5];
    const float* Wv   = (const float*)d_in[6];
    const float* bv   = (const float*)d_in[7];
    const float* Wo   = (const float*)d_in[8];
    const float* bo   = (const float*)d_in[9];
    const float* toep = (const float*)d_in[10];
    float* out = (float*)d_out;

    float *pq, *pk, *pv, *px;
    cudaGetSymbolAddress((void**)&pq, g_q);
    cudaGetSymbolAddress((void**)&pk, g_k);
    cudaGetSymbolAddress((void**)&pv, g_v);
    cudaGetSymbolAddress((void**)&px, g_x);

    const int M = BB * LL;
    const int N = HH * DD;
    const int K = FF;

    dim3 gg(N / 128, M / 128);

    gemm_kernel<<<gg, 256>>>(inq,  Wq, bq, pq, M, N, K, 1);
    gemm_kernel<<<gg, 256>>>(inkv, Wk, bk, pk, M, N, K, 1);
    gemm_kernel<<<gg, 256>>>(inkv, Wv, bv, pv, M, N, K, 1);

    size_t smem = (size_t)(5 * 4096) * sizeof(float);  // 81920 B
    cudaFuncSetAttribute(attn_kernel, cudaFuncAttributeMaxDynamicSharedMemorySize, (int)smem);
    attn_kernel<<<dim3(LL / 64, HH, BB), 256, smem>>>(pq, pk, pv, toep, px);

    gemm_kernel<<<gg, 256>>>(px, Wo, bo, out, M, FF, N, 0);
}

// round 3
// speedup vs baseline: 1.2753x; 1.2753x over previous
#include <cuda_runtime.h>

#define BB 16
#define LL 1024
#define FF 512
#define HH 8
#define DD 64

__device__ float g_q[BB*HH*LL*DD];
__device__ float g_k[BB*HH*LL*DD];
__device__ float g_v[BB*HH*LL*DD];
__device__ float g_x[BB*LL*HH*DD];

// ---------------------------------------------------------------------------
// SGEMM (R1 exact — measured ~75% of fp32 peak): C = A(M,K) @ W(K,N) + bias
// mode 0: row-major out; mode 1: scatter to (B,H,L,D)
// ---------------------------------------------------------------------------
__global__ void __launch_bounds__(256) gemm_kernel(
    const float* __restrict__ A, const float* __restrict__ W,
    const float* __restrict__ bias, float* __restrict__ C,
    int M, int N, int K, int mode)
{
    __shared__ float As[8][128];
    __shared__ float Bs[8][128];

    const int t  = threadIdx.x;
    const int bm = blockIdx.y * 128;
    const int bn = blockIdx.x * 128;
    const int tm = (t >> 4) * 8;
    const int tn = (t & 15) * 8;

    const int ar = t >> 1;
    const int ac = (t & 1) * 4;
    const int wr = t >> 5;
    const int wc = (t & 31) * 4;

    const float* Ap = A + (size_t)(bm + ar) * K + ac;
    const float* Wp = W + (size_t)wr * N + bn + wc;

    float acc[8][8];
    #pragma unroll
    for (int i = 0; i < 8; i++)
        #pragma unroll
        for (int j = 0; j < 8; j++) acc[i][j] = 0.f;

    for (int k0 = 0; k0 < K; k0 += 8) {
        float4 av = *(const float4*)Ap; Ap += 8;
        float4 wv = *(const float4*)Wp; Wp += (size_t)8 * N;

        __syncthreads();
        As[ac + 0][ar] = av.x;
        As[ac + 1][ar] = av.y;
        As[ac + 2][ar] = av.z;
        As[ac + 3][ar] = av.w;
        *(float4*)&Bs[wr][wc] = wv;
        __syncthreads();

        #pragma unroll
        for (int kk = 0; kk < 8; kk++) {
            float a[8], b[8];
            *(float4*)(a    ) = *(const float4*)&As[kk][tm];
            *(float4*)(a + 4) = *(const float4*)&As[kk][tm + 4];
            *(float4*)(b    ) = *(const float4*)&Bs[kk][tn];
            *(float4*)(b + 4) = *(const float4*)&Bs[kk][tn + 4];
            #pragma unroll
            for (int i = 0; i < 8; i++)
                #pragma unroll
                for (int j = 0; j < 8; j++)
                    acc[i][j] += a[i] * b[j];
        }
    }

    if (mode == 0) {
        #pragma unroll
        for (int i = 0; i < 8; i++) {
            int gm = bm + tm + i;
            float* cp = C + (size_t)gm * N + bn + tn;
            #pragma unroll
            for (int j = 0; j < 8; j++)
                cp[j] = acc[i][j] + bias[bn + tn + j];
        }
    } else {
        #pragma unroll
        for (int i = 0; i < 8; i++) {
            int gm = bm + tm + i;
            int b_ = gm >> 10;
            int l_ = gm & 1023;
            #pragma unroll
            for (int j = 0; j < 8; j++) {
                int gn = bn + tn + j;
                int h_ = gn >> 6;
                int d_ = gn & 63;
                C[(((size_t)(b_ * HH + h_)) * LL + l_) * DD + d_] = acc[i][j] + bias[gn];
            }
        }
    }
}

// ---------------------------------------------------------------------------
// Flash attention: float4 inner-product form, pad-68 strides (no swizzle ALU,
// no transpose). Tile 64x64, 256 thr = 16x16 grid, 4x4 per-thread S tile.
// Stride 68 floats = 272B: 16B-aligned, 68 mod 32 = 4 -> <=2-way conflicts.
// ---------------------------------------------------------------------------
#define ST 68

__global__ void __launch_bounds__(256, 2) attn_kernel(
    const float* __restrict__ q, const float* __restrict__ k,
    const float* __restrict__ v, const float* __restrict__ toep,
    float* __restrict__ x)
{
    extern __shared__ float sm[];
    float* Qs = sm;                 // [64][ST]
    float* Ks = Qs + 64 * ST;       // [64][ST]  (key, d)
    float* Vs = Ks + 64 * ST;       // [64][ST]  (key, d)
    float* Ps = Vs + 64 * ST;       // [64][ST]  (qrow, key)
    float* Tp = Ps + 64 * ST;       // [4096]

    const int t  = threadIdx.x;
    const int qt = blockIdx.x;
    const int h  = blockIdx.y;
    const int b  = blockIdx.z;
    const int bh = b * HH + h;

    const float* qb = q + (size_t)bh * LL * DD + (size_t)qt * 64 * DD;
    const float* kb = k + (size_t)bh * LL * DD;
    const float* vb = v + (size_t)bh * LL * DD;

    {
        const float4* qg = (const float4*)qb;
        const float4* tg = (const float4*)(toep + (size_t)h * 4096);
        #pragma unroll
        for (int ch = 0; ch < 4; ch++) {
            int fi = ch * 256 + t;           // 0..1023
            int row = fi >> 4;
            int c   = fi & 15;
            *(float4*)&Qs[row * ST + c * 4] = qg[fi];
            *(float4*)&Tp[fi * 4] = tg[fi];
        }
    }

    const int ty = t >> 4;
    const int tx = t & 15;
    const int rq = ty * 4;     // this thread's first q-row in tile
    const int ck = tx * 4;     // this thread's first key / d col

    float m_[4], l_[4], o[4][4];
    #pragma unroll
    for (int i = 0; i < 4; i++) {
        m_[i] = -1e30f; l_[i] = 0.f;
        #pragma unroll
        for (int c = 0; c < 4; c++) o[i][c] = 0.f;
    }

    int qxi[4], qyi[4];
    #pragma unroll
    for (int i = 0; i < 4; i++) {
        int qr = qt * 64 + rq + i;
        qxi[i] = qr >> 5;
        qyi[i] = qr & 31;
    }

    const float scale = 0.125f;

    for (int kt = 0; kt < 16; kt++) {
        const float4* kg = (const float4*)(kb + (size_t)kt * 64 * DD);
        const float4* vg = (const float4*)(vb + (size_t)kt * 64 * DD);
        #pragma unroll
        for (int ch = 0; ch < 4; ch++) {
            int fi = ch * 256 + t;
            int row = fi >> 4;
            int c   = fi & 15;
            *(float4*)&Ks[row * ST + c * 4] = kg[fi];
            *(float4*)&Vs[row * ST + c * 4] = vg[fi];
        }
        __syncthreads();

        // S = Q @ K^T  (float4 dot over d)
        float s4[4][4];
        #pragma unroll
        for (int i = 0; i < 4; i++)
            #pragma unroll
            for (int j = 0; j < 4; j++) s4[i][j] = 0.f;

        #pragma unroll 4
        for (int c = 0; c < 16; c++) {
            float4 a[4], bb[4];
            #pragma unroll
            for (int i = 0; i < 4; i++)
                a[i] = *(const float4*)&Qs[(rq + i) * ST + c * 4];
            #pragma unroll
            for (int j = 0; j < 4; j++)
                bb[j] = *(const float4*)&Ks[(ck + j) * ST + c * 4];
            #pragma unroll
            for (int i = 0; i < 4; i++)
                #pragma unroll
                for (int j = 0; j < 4; j++)
                    s4[i][j] += a[i].x * bb[j].x + a[i].y * bb[j].y
                              + a[i].z * bb[j].z + a[i].w * bb[j].w;
        }

        // scale + toeplitz bias
        #pragma unroll
        for (int i = 0; i < 4; i++) {
            #pragma unroll
            for (int j = 0; j < 4; j++) {
                int kc = kt * 64 + ck + j;
                int dx = qxi[i] - (kc >> 5) + 32;
                int dy = qyi[i] - (kc & 31) + 32;
                s4[i][j] = s4[i][j] * scale + Tp[dx * 64 + dy];
            }
        }

        // online softmax across 16 tx lanes
        #pragma unroll
        for (int i = 0; i < 4; i++) {
            float tmax = fmaxf(fmaxf(s4[i][0], s4[i][1]), fmaxf(s4[i][2], s4[i][3]));
            #pragma unroll
            for (int off = 8; off >= 1; off >>= 1)
                tmax = fmaxf(tmax, __shfl_xor_sync(0xffffffffu, tmax, off));
            float nm = fmaxf(m_[i], tmax);
            float al = __expf(m_[i] - nm);
            float ts = 0.f;
            #pragma unroll
            for (int j = 0; j < 4; j++) {
                s4[i][j] = __expf(s4[i][j] - nm);
                ts += s4[i][j];
            }
            #pragma unroll
            for (int off = 8; off >= 1; off >>= 1)
                ts += __shfl_xor_sync(0xffffffffu, ts, off);
            l_[i] = l_[i] * al + ts;
            m_[i] = nm;
            #pragma unroll
            for (int c = 0; c < 4; c++) o[i][c] *= al;
            float4 pv = make_float4(s4[i][0], s4[i][1], s4[i][2], s4[i][3]);
            *(float4*)&Ps[(rq + i) * ST + ck] = pv;
        }
        __syncthreads();

        // O += P @ V  (key chunks of 4)
        #pragma unroll 4
        for (int c = 0; c < 16; c++) {
            float4 a[4], bb[4];
            #pragma unroll
            for (int i = 0; i < 4; i++)
                a[i] = *(const float4*)&Ps[(rq + i) * ST + c * 4];
            #pragma unroll
            for (int kk = 0; kk < 4; kk++)
                bb[kk] = *(const float4*)&Vs[(c * 4 + kk) * ST + ck];
            #pragma unroll
            for (int i = 0; i < 4; i++) {
                o[i][0] += a[i].x * bb[0].x + a[i].y * bb[1].x + a[i].z * bb[2].x + a[i].w * bb[3].x;
                o[i][1] += a[i].x * bb[0].y + a[i].y * bb[1].y + a[i].z * bb[2].y + a[i].w * bb[3].y;
                o[i][2] += a[i].x * bb[0].z + a[i].y * bb[1].z + a[i].z * bb[2].z + a[i].w * bb[3].z;
                o[i][3] += a[i].x * bb[0].w + a[i].y * bb[1].w + a[i].z * bb[2].w + a[i].w * bb[3].w;
            }
        }
        __syncthreads();
    }

    #pragma unroll
    for (int i = 0; i < 4; i++) {
        float inv = 1.0f / l_[i];
        int qrow = qt * 64 + rq + i;
        float4 val;
        val.x = o[i][0] * inv; val.y = o[i][1] * inv;
        val.z = o[i][2] * inv; val.w = o[i][3] * inv;
        *(float4*)&x[((size_t)(b * LL + qrow)) * (HH * DD) + h * DD + ck] = val;
    }
}

// ---------------------------------------------------------------------------
extern "C" void kernel_launch(void* const* d_in, const int* in_sizes, int n_in,
                              void* d_out, int out_size)
{
    const float* inq  = (const float*)d_in[0];
    const float* inkv = (const float*)d_in[1];
    const float* Wq   = (const float*)d_in[2];
    const float* bq   = (const float*)d_in[3];
    const float* Wk   = (const float*)d_in[4];
    const float* bk   = (const float*)d_in[5];
    const float* Wv   = (const float*)d_in[6];
    const float* bv   = (const float*)d_in[7];
    const float* Wo   = (const float*)d_in[8];
    const float* bo   = (const float*)d_in[9];
    const float* toep = (const float*)d_in[10];
    float* out = (float*)d_out;

    float *pq, *pk, *pv, *px;
    cudaGetSymbolAddress((void**)&pq, g_q);
    cudaGetSymbolAddress((void**)&pk, g_k);
    cudaGetSymbolAddress((void**)&pv, g_v);
    cudaGetSymbolAddress((void**)&px, g_x);

    const int M = BB * LL;
    const int N = HH * DD;
    const int K = FF;

    dim3 gg(N / 128, M / 128);

    gemm_kernel<<<gg, 256>>>(inq,  Wq, bq, pq, M, N, K, 1);
    gemm_kernel<<<gg, 256>>>(inkv, Wk, bk, pk, M, N, K, 1);
    gemm_kernel<<<gg, 256>>>(inkv, Wv, bv, pv, M, N, K, 1);

    size_t smem = (size_t)(4 * 64 * ST + 4096) * sizeof(float);  // 86016 B
    cudaFuncSetAttribute(attn_kernel, cudaFuncAttributeMaxDynamicSharedMemorySize, (int)smem);
    attn_kernel<<<dim3(LL / 64, HH, BB), 256, smem>>>(pq, pk, pv, toep, px);

    gemm_kernel<<<gg, 256>>>(px, Wo, bo, out, M, FF, N, 0);
}

// round 5
// speedup vs baseline: 1.6789x; 1.3165x over previous
#include <cuda_runtime.h>

#define BB 16
#define LL 1024
#define FF 512
#define HH 8
#define DD 64

__device__ float g_q[BB*HH*LL*DD];
__device__ float g_kT[BB*HH*DD*LL];   // K transposed: [b][h][d][l]
__device__ float g_v[BB*HH*LL*DD];
__device__ float g_x[BB*LL*HH*DD];

// ---------------------------------------------------------------------------
// SGEMM (R1 structure): C = A(M,K) @ W(K,N) + bias
// mode 0: row-major [M,N]; mode 1: scatter (B,H,L,D); mode 2: scatter (B,H,D,L)
// ---------------------------------------------------------------------------
__global__ void __launch_bounds__(256) gemm_kernel(
    const float* __restrict__ A, const float* __restrict__ W,
    const float* __restrict__ bias, float* __restrict__ C,
    int M, int N, int K, int mode)
{
    __shared__ float As[8][128];
    __shared__ float Bs[8][128];

    const int t  = threadIdx.x;
    const int bm = blockIdx.y * 128;
    const int bn = blockIdx.x * 128;
    const int tm = (t >> 4) * 8;
    const int tn = (t & 15) * 8;

    const int ar = t >> 1;
    const int ac = (t & 1) * 4;
    const int wr = t >> 5;
    const int wc = (t & 31) * 4;

    const float* Ap = A + (size_t)(bm + ar) * K + ac;
    const float* Wp = W + (size_t)wr * N + bn + wc;

    float acc[8][8];
    #pragma unroll
    for (int i = 0; i < 8; i++)
        #pragma unroll
        for (int j = 0; j < 8; j++) acc[i][j] = 0.f;

    for (int k0 = 0; k0 < K; k0 += 8) {
        float4 av = *(const float4*)Ap; Ap += 8;
        float4 wv = *(const float4*)Wp; Wp += (size_t)8 * N;

        __syncthreads();
        As[ac + 0][ar] = av.x;
        As[ac + 1][ar] = av.y;
        As[ac + 2][ar] = av.z;
        As[ac + 3][ar] = av.w;
        *(float4*)&Bs[wr][wc] = wv;
        __syncthreads();

        #pragma unroll
        for (int kk = 0; kk < 8; kk++) {
            float a[8], b[8];
            *(float4*)(a    ) = *(const float4*)&As[kk][tm];
            *(float4*)(a + 4) = *(const float4*)&As[kk][tm + 4];
            *(float4*)(b    ) = *(const float4*)&Bs[kk][tn];
            *(float4*)(b + 4) = *(const float4*)&Bs[kk][tn + 4];
            #pragma unroll
            for (int i = 0; i < 8; i++)
                #pragma unroll
                for (int j = 0; j < 8; j++)
                    acc[i][j] += a[i] * b[j];
        }
    }

    if (mode == 0) {
        #pragma unroll
        for (int i = 0; i < 8; i++) {
            int gm = bm + tm + i;
            float* cp = C + (size_t)gm * N + bn + tn;
            #pragma unroll
            for (int j = 0; j < 8; j++)
                cp[j] = acc[i][j] + bias[bn + tn + j];
        }
    } else if (mode == 1) {
        #pragma unroll
        for (int i = 0; i < 8; i++) {
            int gm = bm + tm + i;
            int b_ = gm >> 10;
            int l_ = gm & 1023;
            #pragma unroll
            for (int j = 0; j < 8; j++) {
                int gn = bn + tn + j;
                int h_ = gn >> 6;
                int d_ = gn & 63;
                C[(((size_t)(b_ * HH + h_)) * LL + l_) * DD + d_] = acc[i][j] + bias[gn];
            }
        }
    } else {   // mode 2: K^T scatter [b][h][d][l]
        #pragma unroll
        for (int i = 0; i < 8; i++) {
            int gm = bm + tm + i;
            int b_ = gm >> 10;
            int l_ = gm & 1023;
            #pragma unroll
            for (int j = 0; j < 8; j++) {
                int gn = bn + tn + j;
                int h_ = gn >> 6;
                int d_ = gn & 63;
                C[(((size_t)(b_ * HH + h_)) * DD + d_) * LL + l_] = acc[i][j] + bias[gn];
            }
        }
    }
}

// ---------------------------------------------------------------------------
// Flash attention, 128x128 tile, 256 threads, 8x8 per-thread (2x2 split of
// 4x4 blocks, groups +-64). All compute loads are conflict-free LDS.128.
// K comes in pre-transposed [b][h][d][l].
// ---------------------------------------------------------------------------
#define QS_ST 68
#define KT_ST 132
#define VS_ST 68
#define PS_ST 132

__global__ void __launch_bounds__(256, 1) attn_kernel(
    const float* __restrict__ q, const float* __restrict__ kT,
    const float* __restrict__ v, const float* __restrict__ toep,
    float* __restrict__ x)
{
    extern __shared__ float sm[];
    float* Qs = sm;                      // [128][QS_ST]
    float* Kt = Qs + 128 * QS_ST;        // [64][KT_ST]  (d, key)
    float* Vs = Kt + 64 * KT_ST;         // [128][VS_ST] (key, d)
    float* Ps = Vs + 128 * VS_ST;        // [128][PS_ST] (row, key)
    float* Tp = Ps + 128 * PS_ST;        // [4096]

    const int t  = threadIdx.x;
    const int qt = blockIdx.x;           // 0..7, tiles of 128 q-rows
    const int h  = blockIdx.y;
    const int b  = blockIdx.z;
    const int bh = b * HH + h;

    const float* qb = q  + (size_t)bh * LL * DD + (size_t)qt * 128 * DD;
    const float* kb = kT + (size_t)bh * DD * LL;
    const float* vb = v  + (size_t)bh * LL * DD;

    // Load Q tile + toeplitz row
    {
        const float4* qg = (const float4*)qb;
        #pragma unroll
        for (int ch = 0; ch < 8; ch++) {
            int fi = ch * 256 + t;
            int row = fi >> 4, dc = fi & 15;
            *(float4*)&Qs[row * QS_ST + dc * 4] = qg[fi];
        }
        const float4* tg = (const float4*)(toep + (size_t)h * 4096);
        #pragma unroll
        for (int ch = 0; ch < 4; ch++) {
            int fi = ch * 256 + t;
            *(float4*)&Tp[fi * 4] = tg[fi];
        }
    }

    const int ty4 = (t >> 4) * 4;        // first row in group
    const int tx4 = (t & 15) * 4;        // first key / d col in group

    float m_[2][4], l_[2][4], o[2][4][4];
    #pragma unroll
    for (int rg = 0; rg < 2; rg++)
        #pragma unroll
        for (int i = 0; i < 4; i++) {
            m_[rg][i] = -1e30f; l_[rg][i] = 0.f;
            #pragma unroll
            for (int c = 0; c < 4; c++) o[rg][i][c] = 0.f;
        }

    int qoff[2][4];
    #pragma unroll
    for (int rg = 0; rg < 2; rg++)
        #pragma unroll
        for (int i = 0; i < 4; i++) {
            int qr = qt * 128 + rg * 64 + ty4 + i;
            qoff[rg][i] = (qr >> 5) * 64 + (qr & 31) + 2080;   // +32*64+32
        }

    const float scale = 0.125f;

    for (int kt = 0; kt < 8; kt++) {
        // load K tile (d-major) and V tile
        #pragma unroll
        for (int ch = 0; ch < 8; ch++) {
            int fi = ch * 256 + t;
            int d = fi >> 5, kc = fi & 31;
            *(float4*)&Kt[d * KT_ST + kc * 4] =
                *(const float4*)(kb + (size_t)d * LL + kt * 128 + kc * 4);
        }
        {
            const float4* vg = (const float4*)(vb + (size_t)kt * 128 * DD);
            #pragma unroll
            for (int ch = 0; ch < 8; ch++) {
                int fi = ch * 256 + t;
                int key = fi >> 4, dc = fi & 15;
                *(float4*)&Vs[key * VS_ST + dc * 4] = vg[fi];
            }
        }
        __syncthreads();

        // per-thread key bias offsets
        int koff[2][4];
        #pragma unroll
        for (int kg = 0; kg < 2; kg++)
            #pragma unroll
            for (int j = 0; j < 4; j++) {
                int kc = kt * 128 + kg * 64 + tx4 + j;
                koff[kg][j] = (kc >> 5) * 64 + (kc & 31);
            }

        // S = Q @ K^T
        float s[2][4][8];
        #pragma unroll
        for (int rg = 0; rg < 2; rg++)
            #pragma unroll
            for (int i = 0; i < 4; i++)
                #pragma unroll
                for (int j = 0; j < 8; j++) s[rg][i][j] = 0.f;

        #pragma unroll 1
        for (int dc = 0; dc < 16; dc++) {
            float4 a[2][4];
            #pragma unroll
            for (int rg = 0; rg < 2; rg++)
                #pragma unroll
                for (int i = 0; i < 4; i++)
                    a[rg][i] = *(const float4*)&Qs[(rg * 64 + ty4 + i) * QS_ST + dc * 4];
            #pragma unroll
            for (int dd = 0; dd < 4; dd++) {
                float4 b0 = *(const float4*)&Kt[(dc * 4 + dd) * KT_ST + tx4];
                float4 b1 = *(const float4*)&Kt[(dc * 4 + dd) * KT_ST + 64 + tx4];
                #pragma unroll
                for (int rg = 0; rg < 2; rg++)
                    #pragma unroll
                    for (int i = 0; i < 4; i++) {
                        float av = ((const float*)&a[rg][i])[dd];
                        s[rg][i][0] += av * b0.x;
                        s[rg][i][1] += av * b0.y;
                        s[rg][i][2] += av * b0.z;
                        s[rg][i][3] += av * b0.w;
                        s[rg][i][4] += av * b1.x;
                        s[rg][i][5] += av * b1.y;
                        s[rg][i][6] += av * b1.z;
                        s[rg][i][7] += av * b1.w;
                    }
            }
        }

        // bias + online softmax (reduce over 16 tx lanes)
        #pragma unroll
        for (int rg = 0; rg < 2; rg++)
            #pragma unroll
            for (int i = 0; i < 4; i++) {
                float* sr = s[rg][i];
                #pragma unroll
                for (int kg = 0; kg < 2; kg++)
                    #pragma unroll
                    for (int j = 0; j < 4; j++)
                        sr[kg * 4 + j] = sr[kg * 4 + j] * scale
                                       + Tp[qoff[rg][i] - koff[kg][j]];
                float mx = sr[0];
                #pragma unroll
                for (int j = 1; j < 8; j++) mx = fmaxf(mx, sr[j]);
                #pragma unroll
                for (int off = 8; off >= 1; off >>= 1)
                    mx = fmaxf(mx, __shfl_xor_sync(0xffffffffu, mx, off));
                float nm = fmaxf(m_[rg][i], mx);
                float al = __expf(m_[rg][i] - nm);
                float ts = 0.f;
                #pragma unroll
                for (int j = 0; j < 8; j++) {
                    sr[j] = __expf(sr[j] - nm);
                    ts += sr[j];
                }
                #pragma unroll
                for (int off = 8; off >= 1; off >>= 1)
                    ts += __shfl_xor_sync(0xffffffffu, ts, off);
                l_[rg][i] = l_[rg][i] * al + ts;
                m_[rg][i] = nm;
                #pragma unroll
                for (int c = 0; c < 4; c++) o[rg][i][c] *= al;
                int row = rg * 64 + ty4 + i;
                *(float4*)&Ps[row * PS_ST + tx4]      = make_float4(sr[0], sr[1], sr[2], sr[3]);
                *(float4*)&Ps[row * PS_ST + 64 + tx4] = make_float4(sr[4], sr[5], sr[6], sr[7]);
            }
        __syncthreads();

        // O += P @ V
        #pragma unroll 1
        for (int kc = 0; kc < 32; kc++) {
            float4 a[2][4];
            #pragma unroll
            for (int rg = 0; rg < 2; rg++)
                #pragma unroll
                for (int i = 0; i < 4; i++)
                    a[rg][i] = *(const float4*)&Ps[(rg * 64 + ty4 + i) * PS_ST + kc * 4];
            float4 v0 = *(const float4*)&Vs[(kc * 4 + 0) * VS_ST + tx4];
            float4 v1 = *(const float4*)&Vs[(kc * 4 + 1) * VS_ST + tx4];
            float4 v2 = *(const float4*)&Vs[(kc * 4 + 2) * VS_ST + tx4];
            float4 v3 = *(const float4*)&Vs[(kc * 4 + 3) * VS_ST + tx4];
            #pragma unroll
            for (int rg = 0; rg < 2; rg++)
                #pragma unroll
                for (int i = 0; i < 4; i++) {
                    o[rg][i][0] += a[rg][i].x * v0.x + a[rg][i].y * v1.x
                                 + a[rg][i].z * v2.x + a[rg][i].w * v3.x;
                    o[rg][i][1] += a[rg][i].x * v0.y + a[rg][i].y * v1.y
                                 + a[rg][i].z * v2.y + a[rg][i].w * v3.y;
                    o[rg][i][2] += a[rg][i].x * v0.z + a[rg][i].y * v1.z
                                 + a[rg][i].z * v2.z + a[rg][i].w * v3.z;
                    o[rg][i][3] += a[rg][i].x * v0.w + a[rg][i].y * v1.w
                                 + a[rg][i].z * v2.w + a[rg][i].w * v3.w;
                }
        }
        __syncthreads();
    }

    // write x in (B, L, H*D) layout
    #pragma unroll
    for (int rg = 0; rg < 2; rg++)
        #pragma unroll
        for (int i = 0; i < 4; i++) {
            float inv = 1.0f / l_[rg][i];
            int qrow = qt * 128 + rg * 64 + ty4 + i;
            float4 val;
            val.x = o[rg][i][0] * inv; val.y = o[rg][i][1] * inv;
            val.z = o[rg][i][2] * inv; val.w = o[rg][i][3] * inv;
            *(float4*)&x[((size_t)(b * LL + qrow)) * (HH * DD) + h * DD + tx4] = val;
        }
}

// ---------------------------------------------------------------------------
extern "C" void kernel_launch(void* const* d_in, const int* in_sizes, int n_in,
                              void* d_out, int out_size)
{
    const float* inq  = (const float*)d_in[0];
    const float* inkv = (const float*)d_in[1];
    const float* Wq   = (const float*)d_in[2];
    const float* bq   = (const float*)d_in[3];
    const float* Wk   = (const float*)d_in[4];
    const float* bk   = (const float*)d_in[5];
    const float* Wv   = (const float*)d_in[6];
    const float* bv   = (const float*)d_in[7];
    const float* Wo   = (const float*)d_in[8];
    const float* bo   = (const float*)d_in[9];
    const float* toep = (const float*)d_in[10];
    float* out = (float*)d_out;

    float *pq, *pkT, *pv, *px;
    cudaGetSymbolAddress((void**)&pq,  g_q);
    cudaGetSymbolAddress((void**)&pkT, g_kT);
    cudaGetSymbolAddress((void**)&pv,  g_v);
    cudaGetSymbolAddress((void**)&px,  g_x);

    const int M = BB * LL;
    const int N = HH * DD;
    const int K = FF;

    dim3 gg(N / 128, M / 128);

    gemm_kernel<<<gg, 256>>>(inq,  Wq, bq, pq,  M, N, K, 1);
    gemm_kernel<<<gg, 256>>>(inkv, Wk, bk, pkT, M, N, K, 2);
    gemm_kernel<<<gg, 256>>>(inkv, Wv, bv, pv,  M, N, K, 1);

    size_t smem = (size_t)(128 * QS_ST + 64 * KT_ST + 128 * VS_ST
                         + 128 * PS_ST + 4096) * sizeof(float);   // 187392 B
    cudaFuncSetAttribute(attn_kernel, cudaFuncAttributeMaxDynamicSharedMemorySize, (int)smem);
    attn_kernel<<<dim3(8, HH, BB), 256, smem>>>(pq, pkT, pv, toep, px);

    gemm_kernel<<<gg, 256>>>(px, Wo, bo, out, M, FF, N, 0);
}

// round 6
// speedup vs baseline: 2.9667x; 1.7671x over previous
#include <cuda_runtime.h>
#include <cuda_bf16.h>
#include <cstdint>

#define BB 16
#define LL 1024
#define FF 512
#define HH 8
#define DD 64

__device__ float g_q[BB*HH*LL*DD];
__device__ float g_kT[BB*HH*DD*LL];   // K transposed: [b][h][d][l]
__device__ float g_v[BB*HH*LL*DD];
__device__ float g_x[BB*LL*HH*DD];

// ===========================================================================
// mma.sync helpers (sm_80-class, valid on base sm_103 target)
// ===========================================================================
__device__ __forceinline__ uint32_t s2u(const void* p) {
    return (uint32_t)__cvta_generic_to_shared(p);
}
__device__ __forceinline__ void ldsm4(uint32_t* r, uint32_t a) {
    asm volatile("ldmatrix.sync.aligned.m8n8.x4.shared.b16 {%0,%1,%2,%3}, [%4];"
                 : "=r"(r[0]), "=r"(r[1]), "=r"(r[2]), "=r"(r[3]) : "r"(a));
}
__device__ __forceinline__ void ldsm4t(uint32_t* r, uint32_t a) {
    asm volatile("ldmatrix.sync.aligned.m8n8.x4.trans.shared.b16 {%0,%1,%2,%3}, [%4];"
                 : "=r"(r[0]), "=r"(r[1]), "=r"(r[2]), "=r"(r[3]) : "r"(a));
}
__device__ __forceinline__ void mma_bf16(float* c, const uint32_t* a, const uint32_t* b) {
    asm volatile(
        "mma.sync.aligned.m16n8k16.row.col.f32.bf16.bf16.f32 "
        "{%0,%1,%2,%3}, {%4,%5,%6,%7}, {%8,%9}, {%0,%1,%2,%3};"
        : "+f"(c[0]), "+f"(c[1]), "+f"(c[2]), "+f"(c[3])
        : "r"(a[0]), "r"(a[1]), "r"(a[2]), "r"(a[3]), "r"(b[0]), "r"(b[1]));
}
// pack two floats as bf16x2 {lo: a, hi: b}
__device__ __forceinline__ uint32_t packbf(float a, float b) {
    uint32_t r;
    asm("cvt.rn.bf16x2.f32 %0, %1, %2;" : "=r"(r) : "f"(b), "f"(a));
    return r;
}

// ===========================================================================
// Tensor-core split-bf16 GEMM: C = A(16384,512) @ W(512,512) + bias
// 3 passes: hi*hi + hi*lo + lo*hi. CTA 128x128, 8 warps (2Mx4N), warp 64x32.
// mode 0: row-major [M,512]; mode 1: scatter (B,H,L,D); mode 2: scatter (B,H,D,L)
// ===========================================================================
#define SA 40    // A smem row stride in bf16 (pad: conflict-free ldmatrix)
#define SB 136   // B smem row stride in bf16

__global__ void __launch_bounds__(256) gemm_mma(
    const float* __restrict__ A, const float* __restrict__ W,
    const float* __restrict__ bias, float* __restrict__ C, int mode)
{
    __shared__ uint32_t AhU[128 * SA / 2], AlU[128 * SA / 2];
    __shared__ uint32_t BhU[32 * SB / 2],  BlU[32 * SB / 2];

    const int t    = threadIdx.x;
    const int warp = t >> 5;
    const int lane = t & 31;
    const int bm   = blockIdx.y * 128;
    const int bn   = blockIdx.x * 128;
    const int wm   = (warp >> 2) * 64;
    const int wn   = (warp & 3) * 32;

    float acc[4][4][4];
    #pragma unroll
    for (int mt = 0; mt < 4; mt++)
        #pragma unroll
        for (int nt = 0; nt < 4; nt++)
            #pragma unroll
            for (int i = 0; i < 4; i++) acc[mt][nt][i] = 0.f;

    for (int c = 0; c < 16; c++) {
        const int k0 = c * 32;
        __syncthreads();
        // A chunk: 128 rows x 32 k  (4 float4 per thread)
        #pragma unroll
        for (int ch = 0; ch < 4; ch++) {
            int fi = ch * 256 + t;
            int m  = fi >> 3;
            int kc = (fi & 7) * 4;
            float4 v = *(const float4*)(A + (size_t)(bm + m) * 512 + k0 + kc);
            uint32_t h0 = packbf(v.x, v.y), h1 = packbf(v.z, v.w);
            float rx = v.x - __uint_as_float(h0 << 16);
            float ry = v.y - __uint_as_float(h0 & 0xFFFF0000u);
            float rz = v.z - __uint_as_float(h1 << 16);
            float rw = v.w - __uint_as_float(h1 & 0xFFFF0000u);
            int o = m * (SA / 2) + (kc >> 1);
            AhU[o] = h0; AhU[o + 1] = h1;
            AlU[o] = packbf(rx, ry); AlU[o + 1] = packbf(rz, rw);
        }
        // B chunk: 32 k rows x 128 n
        #pragma unroll
        for (int ch = 0; ch < 4; ch++) {
            int fi = ch * 256 + t;
            int kr = fi >> 5;
            int nc = (fi & 31) * 4;
            float4 v = *(const float4*)(W + (size_t)(k0 + kr) * 512 + bn + nc);
            uint32_t h0 = packbf(v.x, v.y), h1 = packbf(v.z, v.w);
            float rx = v.x - __uint_as_float(h0 << 16);
            float ry = v.y - __uint_as_float(h0 & 0xFFFF0000u);
            float rz = v.z - __uint_as_float(h1 << 16);
            float rw = v.w - __uint_as_float(h1 & 0xFFFF0000u);
            int o = kr * (SB / 2) + (nc >> 1);
            BhU[o] = h0; BhU[o + 1] = h1;
            BlU[o] = packbf(rx, ry); BlU[o + 1] = packbf(rz, rw);
        }
        __syncthreads();

        #pragma unroll
        for (int ks = 0; ks < 2; ks++) {
            const int kk = ks * 16;
            // A fragments: row = wm + mt*16 + (lane&15), col = kk + (lane>>4)*8
            uint32_t ah[4][4], al[4][4];
            {
                int arow = (lane & 15);
                int acol = kk + ((lane >> 4) << 3);
                #pragma unroll
                for (int mt = 0; mt < 4; mt++) {
                    int boff = ((wm + mt * 16 + arow) * SA + acol) * 2;
                    ldsm4(ah[mt], s2u((const char*)AhU + boff));
                    ldsm4(al[mt], s2u((const char*)AlU + boff));
                }
            }
            // B fragments: row k = kk + (lane&15), col n = wn + ntp*16 + (lane>>4)*8
            uint32_t bh[4][2], bl[4][2];
            {
                int brow = kk + (lane & 15);
                int bcol = ((lane >> 4) << 3);
                #pragma unroll
                for (int ntp = 0; ntp < 2; ntp++) {
                    int boff = (brow * SB + wn + ntp * 16 + bcol) * 2;
                    uint32_t tmp[4];
                    ldsm4t(tmp, s2u((const char*)BhU + boff));
                    bh[ntp * 2][0] = tmp[0]; bh[ntp * 2][1] = tmp[1];
                    bh[ntp * 2 + 1][0] = tmp[2]; bh[ntp * 2 + 1][1] = tmp[3];
                    ldsm4t(tmp, s2u((const char*)BlU + boff));
                    bl[ntp * 2][0] = tmp[0]; bl[ntp * 2][1] = tmp[1];
                    bl[ntp * 2 + 1][0] = tmp[2]; bl[ntp * 2 + 1][1] = tmp[3];
                }
            }
            #pragma unroll
            for (int mt = 0; mt < 4; mt++)
                #pragma unroll
                for (int nt = 0; nt < 4; nt++) {
                    mma_bf16(acc[mt][nt], ah[mt], bh[nt]);   // hi*hi
                    mma_bf16(acc[mt][nt], ah[mt], bl[nt]);   // hi*lo
                    mma_bf16(acc[mt][nt], al[mt], bh[nt]);   // lo*hi
                }
        }
    }

    // Epilogue: accum layout m16n8: c0,c1 -> (lr, lc),(lr, lc+1); c2,c3 -> row+8
    const int lr = lane >> 2;
    const int lc = (lane & 3) * 2;

    #pragma unroll
    for (int mt = 0; mt < 4; mt++) {
        int r0 = bm + wm + mt * 16 + lr;
        #pragma unroll
        for (int nt = 0; nt < 4; nt++) {
            int col = bn + wn + nt * 8 + lc;
            float b0v = bias[col], b1v = bias[col + 1];
            float* a = acc[mt][nt];
            if (mode == 0) {
                float2 v0 = make_float2(a[0] + b0v, a[1] + b1v);
                float2 v1 = make_float2(a[2] + b0v, a[3] + b1v);
                *(float2*)&C[(size_t)r0 * 512 + col] = v0;
                *(float2*)&C[(size_t)(r0 + 8) * 512 + col] = v1;
            } else if (mode == 1) {
                int h_ = col >> 6, d_ = col & 63;
                #pragma unroll
                for (int rr = 0; rr < 2; rr++) {
                    int r = r0 + rr * 8;
                    int b_ = r >> 10, l_ = r & 1023;
                    float2 v = make_float2(a[rr * 2] + b0v, a[rr * 2 + 1] + b1v);
                    *(float2*)&C[(((size_t)(b_ * HH + h_)) * LL + l_) * DD + d_] = v;
                }
            } else {   // mode 2: K^T scatter [b][h][d][l]
                int h_ = col >> 6, d_ = col & 63;
                #pragma unroll
                for (int rr = 0; rr < 2; rr++) {
                    int r = r0 + rr * 8;
                    int b_ = r >> 10, l_ = r & 1023;
                    size_t base = (((size_t)(b_ * HH + h_)) * DD + d_) * LL + l_;
                    C[base]      = a[rr * 2]     + b0v;
                    C[base + LL] = a[rr * 2 + 1] + b1v;
                }
            }
        }
    }
}

// ---------------------------------------------------------------------------
// Flash attention (R5 exact — 898us): 128x128 tile, 8x8 per-thread split 2x2
// ---------------------------------------------------------------------------
#define QS_ST 68
#define KT_ST 132
#define VS_ST 68
#define PS_ST 132

__global__ void __launch_bounds__(256, 1) attn_kernel(
    const float* __restrict__ q, const float* __restrict__ kT,
    const float* __restrict__ v, const float* __restrict__ toep,
    float* __restrict__ x)
{
    extern __shared__ float sm[];
    float* Qs = sm;
    float* Kt = Qs + 128 * QS_ST;
    float* Vs = Kt + 64 * KT_ST;
    float* Ps = Vs + 128 * VS_ST;
    float* Tp = Ps + 128 * PS_ST;

    const int t  = threadIdx.x;
    const int qt = blockIdx.x;
    const int h  = blockIdx.y;
    const int b  = blockIdx.z;
    const int bh = b * HH + h;

    const float* qb = q  + (size_t)bh * LL * DD + (size_t)qt * 128 * DD;
    const float* kb = kT + (size_t)bh * DD * LL;
    const float* vb = v  + (size_t)bh * LL * DD;

    {
        const float4* qg = (const float4*)qb;
        #pragma unroll
        for (int ch = 0; ch < 8; ch++) {
            int fi = ch * 256 + t;
            int row = fi >> 4, dc = fi & 15;
            *(float4*)&Qs[row * QS_ST + dc * 4] = qg[fi];
        }
        const float4* tg = (const float4*)(toep + (size_t)h * 4096);
        #pragma unroll
        for (int ch = 0; ch < 4; ch++) {
            int fi = ch * 256 + t;
            *(float4*)&Tp[fi * 4] = tg[fi];
        }
    }

    const int ty4 = (t >> 4) * 4;
    const int tx4 = (t & 15) * 4;

    float m_[2][4], l_[2][4], o[2][4][4];
    #pragma unroll
    for (int rg = 0; rg < 2; rg++)
        #pragma unroll
        for (int i = 0; i < 4; i++) {
            m_[rg][i] = -1e30f; l_[rg][i] = 0.f;
            #pragma unroll
            for (int c = 0; c < 4; c++) o[rg][i][c] = 0.f;
        }

    int qoff[2][4];
    #pragma unroll
    for (int rg = 0; rg < 2; rg++)
        #pragma unroll
        for (int i = 0; i < 4; i++) {
            int qr = qt * 128 + rg * 64 + ty4 + i;
            qoff[rg][i] = (qr >> 5) * 64 + (qr & 31) + 2080;
        }

    const float scale = 0.125f;

    for (int kt = 0; kt < 8; kt++) {
        #pragma unroll
        for (int ch = 0; ch < 8; ch++) {
            int fi = ch * 256 + t;
            int d = fi >> 5, kc = fi & 31;
            *(float4*)&Kt[d * KT_ST + kc * 4] =
                *(const float4*)(kb + (size_t)d * LL + kt * 128 + kc * 4);
        }
        {
            const float4* vg = (const float4*)(vb + (size_t)kt * 128 * DD);
            #pragma unroll
            for (int ch = 0; ch < 8; ch++) {
                int fi = ch * 256 + t;
                int key = fi >> 4, dc = fi & 15;
                *(float4*)&Vs[key * VS_ST + dc * 4] = vg[fi];
            }
        }
        __syncthreads();

        int koff[2][4];
        #pragma unroll
        for (int kg = 0; kg < 2; kg++)
            #pragma unroll
            for (int j = 0; j < 4; j++) {
                int kc = kt * 128 + kg * 64 + tx4 + j;
                koff[kg][j] = (kc >> 5) * 64 + (kc & 31);
            }

        float s[2][4][8];
        #pragma unroll
        for (int rg = 0; rg < 2; rg++)
            #pragma unroll
            for (int i = 0; i < 4; i++)
                #pragma unroll
                for (int j = 0; j < 8; j++) s[rg][i][j] = 0.f;

        #pragma unroll 1
        for (int dc = 0; dc < 16; dc++) {
            float4 a[2][4];
            #pragma unroll
            for (int rg = 0; rg < 2; rg++)
                #pragma unroll
                for (int i = 0; i < 4; i++)
                    a[rg][i] = *(const float4*)&Qs[(rg * 64 + ty4 + i) * QS_ST + dc * 4];
            #pragma unroll
            for (int dd = 0; dd < 4; dd++) {
                float4 b0 = *(const float4*)&Kt[(dc * 4 + dd) * KT_ST + tx4];
                float4 b1 = *(const float4*)&Kt[(dc * 4 + dd) * KT_ST + 64 + tx4];
                #pragma unroll
                for (int rg = 0; rg < 2; rg++)
                    #pragma unroll
                    for (int i = 0; i < 4; i++) {
                        float av = ((const float*)&a[rg][i])[dd];
                        s[rg][i][0] += av * b0.x;
                        s[rg][i][1] += av * b0.y;
                        s[rg][i][2] += av * b0.z;
                        s[rg][i][3] += av * b0.w;
                        s[rg][i][4] += av * b1.x;
                        s[rg][i][5] += av * b1.y;
                        s[rg][i][6] += av * b1.z;
                        s[rg][i][7] += av * b1.w;
                    }
            }
        }

        #pragma unroll
        for (int rg = 0; rg < 2; rg++)
            #pragma unroll
            for (int i = 0; i < 4; i++) {
                float* sr = s[rg][i];
                #pragma unroll
                for (int kg = 0; kg < 2; kg++)
                    #pragma unroll
                    for (int j = 0; j < 4; j++)
                        sr[kg * 4 + j] = sr[kg * 4 + j] * scale
                                       + Tp[qoff[rg][i] - koff[kg][j]];
                float mx = sr[0];
                #pragma unroll
                for (int j = 1; j < 8; j++) mx = fmaxf(mx, sr[j]);
                #pragma unroll
                for (int off = 8; off >= 1; off >>= 1)
                    mx = fmaxf(mx, __shfl_xor_sync(0xffffffffu, mx, off));
                float nm = fmaxf(m_[rg][i], mx);
                float al = __expf(m_[rg][i] - nm);
                float ts = 0.f;
                #pragma unroll
                for (int j = 0; j < 8; j++) {
                    sr[j] = __expf(sr[j] - nm);
                    ts += sr[j];
                }
                #pragma unroll
                for (int off = 8; off >= 1; off >>= 1)
                    ts += __shfl_xor_sync(0xffffffffu, ts, off);
                l_[rg][i] = l_[rg][i] * al + ts;
                m_[rg][i] = nm;
                #pragma unroll
                for (int c = 0; c < 4; c++) o[rg][i][c] *= al;
                int row = rg * 64 + ty4 + i;
                *(float4*)&Ps[row * PS_ST + tx4]      = make_float4(sr[0], sr[1], sr[2], sr[3]);
                *(float4*)&Ps[row * PS_ST + 64 + tx4] = make_float4(sr[4], sr[5], sr[6], sr[7]);
            }
        __syncthreads();

        #pragma unroll 1
        for (int kc = 0; kc < 32; kc++) {
            float4 a[2][4];
            #pragma unroll
            for (int rg = 0; rg < 2; rg++)
                #pragma unroll
                for (int i = 0; i < 4; i++)
                    a[rg][i] = *(const float4*)&Ps[(rg * 64 + ty4 + i) * PS_ST + kc * 4];
            float4 v0 = *(const float4*)&Vs[(kc * 4 + 0) * VS_ST + tx4];
            float4 v1 = *(const float4*)&Vs[(kc * 4 + 1) * VS_ST + tx4];
            float4 v2 = *(const float4*)&Vs[(kc * 4 + 2) * VS_ST + tx4];
            float4 v3 = *(const float4*)&Vs[(kc * 4 + 3) * VS_ST + tx4];
            #pragma unroll
            for (int rg = 0; rg < 2; rg++)
                #pragma unroll
                for (int i = 0; i < 4; i++) {
                    o[rg][i][0] += a[rg][i].x * v0.x + a[rg][i].y * v1.x
                                 + a[rg][i].z * v2.x + a[rg][i].w * v3.x;
                    o[rg][i][1] += a[rg][i].x * v0.y + a[rg][i].y * v1.y
                                 + a[rg][i].z * v2.y + a[rg][i].w * v3.y;
                    o[rg][i][2] += a[rg][i].x * v0.z + a[rg][i].y * v1.z
                                 + a[rg][i].z * v2.z + a[rg][i].w * v3.z;
                    o[rg][i][3] += a[rg][i].x * v0.w + a[rg][i].y * v1.w
                                 + a[rg][i].z * v2.w + a[rg][i].w * v3.w;
                }
        }
        __syncthreads();
    }

    #pragma unroll
    for (int rg = 0; rg < 2; rg++)
        #pragma unroll
        for (int i = 0; i < 4; i++) {
            float inv = 1.0f / l_[rg][i];
            int qrow = qt * 128 + rg * 64 + ty4 + i;
            float4 val;
            val.x = o[rg][i][0] * inv; val.y = o[rg][i][1] * inv;
            val.z = o[rg][i][2] * inv; val.w = o[rg][i][3] * inv;
            *(float4*)&x[((size_t)(b * LL + qrow)) * (HH * DD) + h * DD + tx4] = val;
        }
}

// ---------------------------------------------------------------------------
extern "C" void kernel_launch(void* const* d_in, const int* in_sizes, int n_in,
                              void* d_out, int out_size)
{
    const float* inq  = (const float*)d_in[0];
    const float* inkv = (const float*)d_in[1];
    const float* Wq   = (const float*)d_in[2];
    const float* bq   = (const float*)d_in[3];
    const float* Wk   = (const float*)d_in[4];
    const float* bk   = (const float*)d_in[5];
    const float* Wv   = (const float*)d_in[6];
    const float* bv   = (const float*)d_in[7];
    const float* Wo   = (const float*)d_in[8];
    const float* bo   = (const float*)d_in[9];
    const float* toep = (const float*)d_in[10];
    float* out = (float*)d_out;

    float *pq, *pkT, *pv, *px;
    cudaGetSymbolAddress((void**)&pq,  g_q);
    cudaGetSymbolAddress((void**)&pkT, g_kT);
    cudaGetSymbolAddress((void**)&pv,  g_v);
    cudaGetSymbolAddress((void**)&px,  g_x);

    dim3 gg(4, 128);   // N/128, M/128

    gemm_mma<<<gg, 256>>>(inq,  Wq, bq, pq,  1);
    gemm_mma<<<gg, 256>>>(inkv, Wk, bk, pkT, 2);
    gemm_mma<<<gg, 256>>>(inkv, Wv, bv, pv,  1);

    size_t smem = (size_t)(128 * QS_ST + 64 * KT_ST + 128 * VS_ST
                         + 128 * PS_ST + 4096) * sizeof(float);
    cudaFuncSetAttribute(attn_kernel, cudaFuncAttributeMaxDynamicSharedMemorySize, (int)smem);
    attn_kernel<<<dim3(8, HH, BB), 256, smem>>>(pq, pkT, pv, toep, px);

    gemm_mma<<<gg, 256>>>(px, Wo, bo, out, 0);
}

// round 7
// speedup vs baseline: 6.0681x; 2.0454x over previous
#include <cuda_runtime.h>
#include <cuda_bf16.h>
#include <cuda_fp16.h>
#include <cstdint>

#define BB 16
#define LL 1024
#define FF 512
#define HH 8
#define DD 64

__device__ float g_q[BB*HH*LL*DD];
__device__ float g_kT[BB*HH*DD*LL];   // K transposed: [b][h][d][l]
__device__ float g_v[BB*HH*LL*DD];
__device__ float g_x[BB*LL*HH*DD];

// ===========================================================================
// mma.sync helpers
// ===========================================================================
__device__ __forceinline__ uint32_t s2u(const void* p) {
    return (uint32_t)__cvta_generic_to_shared(p);
}
__device__ __forceinline__ void ldsm4(uint32_t* r, uint32_t a) {
    asm volatile("ldmatrix.sync.aligned.m8n8.x4.shared.b16 {%0,%1,%2,%3}, [%4];"
                 : "=r"(r[0]), "=r"(r[1]), "=r"(r[2]), "=r"(r[3]) : "r"(a));
}
__device__ __forceinline__ void ldsm4t(uint32_t* r, uint32_t a) {
    asm volatile("ldmatrix.sync.aligned.m8n8.x4.trans.shared.b16 {%0,%1,%2,%3}, [%4];"
                 : "=r"(r[0]), "=r"(r[1]), "=r"(r[2]), "=r"(r[3]) : "r"(a));
}
__device__ __forceinline__ void mma_bf16(float* c, const uint32_t* a, const uint32_t* b) {
    asm volatile(
        "mma.sync.aligned.m16n8k16.row.col.f32.bf16.bf16.f32 "
        "{%0,%1,%2,%3}, {%4,%5,%6,%7}, {%8,%9}, {%0,%1,%2,%3};"
        : "+f"(c[0]), "+f"(c[1]), "+f"(c[2]), "+f"(c[3])
        : "r"(a[0]), "r"(a[1]), "r"(a[2]), "r"(a[3]), "r"(b[0]), "r"(b[1]));
}
__device__ __forceinline__ void mma_f16(float* c, const uint32_t* a, const uint32_t* b) {
    asm volatile(
        "mma.sync.aligned.m16n8k16.row.col.f32.f16.f16.f32 "
        "{%0,%1,%2,%3}, {%4,%5,%6,%7}, {%8,%9}, {%0,%1,%2,%3};"
        : "+f"(c[0]), "+f"(c[1]), "+f"(c[2]), "+f"(c[3])
        : "r"(a[0]), "r"(a[1]), "r"(a[2]), "r"(a[3]), "r"(b[0]), "r"(b[1]));
}
__device__ __forceinline__ uint32_t packbf(float a, float b) {
    uint32_t r;
    asm("cvt.rn.bf16x2.f32 %0, %1, %2;" : "=r"(r) : "f"(b), "f"(a));
    return r;
}
__device__ __forceinline__ uint32_t packhf(float a, float b) {
    __half2 h = __floats2half2_rn(a, b);
    return *(uint32_t*)&h;
}

// ===========================================================================
// Tensor-core split-bf16 GEMM (R6 exact, validated): C = A @ W + bias
// ===========================================================================
#define SA 40
#define SB 136

__global__ void __launch_bounds__(256) gemm_mma(
    const float* __restrict__ A, const float* __restrict__ W,
    const float* __restrict__ bias, float* __restrict__ C, int mode)
{
    __shared__ uint32_t AhU[128 * SA / 2], AlU[128 * SA / 2];
    __shared__ uint32_t BhU[32 * SB / 2],  BlU[32 * SB / 2];

    const int t    = threadIdx.x;
    const int warp = t >> 5;
    const int lane = t & 31;
    const int bm   = blockIdx.y * 128;
    const int bn   = blockIdx.x * 128;
    const int wm   = (warp >> 2) * 64;
    const int wn   = (warp & 3) * 32;

    float acc[4][4][4];
    #pragma unroll
    for (int mt = 0; mt < 4; mt++)
        #pragma unroll
        for (int nt = 0; nt < 4; nt++)
            #pragma unroll
            for (int i = 0; i < 4; i++) acc[mt][nt][i] = 0.f;

    for (int c = 0; c < 16; c++) {
        const int k0 = c * 32;
        __syncthreads();
        #pragma unroll
        for (int ch = 0; ch < 4; ch++) {
            int fi = ch * 256 + t;
            int m  = fi >> 3;
            int kc = (fi & 7) * 4;
            float4 v = *(const float4*)(A + (size_t)(bm + m) * 512 + k0 + kc);
            uint32_t h0 = packbf(v.x, v.y), h1 = packbf(v.z, v.w);
            float rx = v.x - __uint_as_float(h0 << 16);
            float ry = v.y - __uint_as_float(h0 & 0xFFFF0000u);
            float rz = v.z - __uint_as_float(h1 << 16);
            float rw = v.w - __uint_as_float(h1 & 0xFFFF0000u);
            int o = m * (SA / 2) + (kc >> 1);
            AhU[o] = h0; AhU[o + 1] = h1;
            AlU[o] = packbf(rx, ry); AlU[o + 1] = packbf(rz, rw);
        }
        #pragma unroll
        for (int ch = 0; ch < 4; ch++) {
            int fi = ch * 256 + t;
            int kr = fi >> 5;
            int nc = (fi & 31) * 4;
            float4 v = *(const float4*)(W + (size_t)(k0 + kr) * 512 + bn + nc);
            uint32_t h0 = packbf(v.x, v.y), h1 = packbf(v.z, v.w);
            float rx = v.x - __uint_as_float(h0 << 16);
            float ry = v.y - __uint_as_float(h0 & 0xFFFF0000u);
            float rz = v.z - __uint_as_float(h1 << 16);
            float rw = v.w - __uint_as_float(h1 & 0xFFFF0000u);
            int o = kr * (SB / 2) + (nc >> 1);
            BhU[o] = h0; BhU[o + 1] = h1;
            BlU[o] = packbf(rx, ry); BlU[o + 1] = packbf(rz, rw);
        }
        __syncthreads();

        #pragma unroll
        for (int ks = 0; ks < 2; ks++) {
            const int kk = ks * 16;
            uint32_t ah[4][4], al[4][4];
            {
                int arow = (lane & 15);
                int acol = kk + ((lane >> 4) << 3);
                #pragma unroll
                for (int mt = 0; mt < 4; mt++) {
                    int boff = ((wm + mt * 16 + arow) * SA + acol) * 2;
                    ldsm4(ah[mt], s2u((const char*)AhU + boff));
                    ldsm4(al[mt], s2u((const char*)AlU + boff));
                }
            }
            uint32_t bh[4][2], bl[4][2];
            {
                int brow = kk + (lane & 15);
                int bcol = ((lane >> 4) << 3);
                #pragma unroll
                for (int ntp = 0; ntp < 2; ntp++) {
                    int boff = (brow * SB + wn + ntp * 16 + bcol) * 2;
                    uint32_t tmp[4];
                    ldsm4t(tmp, s2u((const char*)BhU + boff));
                    bh[ntp * 2][0] = tmp[0]; bh[ntp * 2][1] = tmp[1];
                    bh[ntp * 2 + 1][0] = tmp[2]; bh[ntp * 2 + 1][1] = tmp[3];
                    ldsm4t(tmp, s2u((const char*)BlU + boff));
                    bl[ntp * 2][0] = tmp[0]; bl[ntp * 2][1] = tmp[1];
                    bl[ntp * 2 + 1][0] = tmp[2]; bl[ntp * 2 + 1][1] = tmp[3];
                }
            }
            #pragma unroll
            for (int mt = 0; mt < 4; mt++)
                #pragma unroll
                for (int nt = 0; nt < 4; nt++) {
                    mma_bf16(acc[mt][nt], ah[mt], bh[nt]);
                    mma_bf16(acc[mt][nt], ah[mt], bl[nt]);
                    mma_bf16(acc[mt][nt], al[mt], bh[nt]);
                }
        }
    }

    const int lr = lane >> 2;
    const int lc = (lane & 3) * 2;

    #pragma unroll
    for (int mt = 0; mt < 4; mt++) {
        int r0 = bm + wm + mt * 16 + lr;
        #pragma unroll
        for (int nt = 0; nt < 4; nt++) {
            int col = bn + wn + nt * 8 + lc;
            float b0v = bias[col], b1v = bias[col + 1];
            float* a = acc[mt][nt];
            if (mode == 0) {
                *(float2*)&C[(size_t)r0 * 512 + col] = make_float2(a[0] + b0v, a[1] + b1v);
                *(float2*)&C[(size_t)(r0 + 8) * 512 + col] = make_float2(a[2] + b0v, a[3] + b1v);
            } else if (mode == 1) {
                int h_ = col >> 6, d_ = col & 63;
                #pragma unroll
                for (int rr = 0; rr < 2; rr++) {
                    int r = r0 + rr * 8;
                    int b_ = r >> 10, l_ = r & 1023;
                    *(float2*)&C[(((size_t)(b_ * HH + h_)) * LL + l_) * DD + d_] =
                        make_float2(a[rr * 2] + b0v, a[rr * 2 + 1] + b1v);
                }
            } else {
                int h_ = col >> 6, d_ = col & 63;
                #pragma unroll
                for (int rr = 0; rr < 2; rr++) {
                    int r = r0 + rr * 8;
                    int b_ = r >> 10, l_ = r & 1023;
                    size_t base = (((size_t)(b_ * HH + h_)) * DD + d_) * LL + l_;
                    C[base]      = a[rr * 2]     + b0v;
                    C[base + LL] = a[rr * 2 + 1] + b1v;
                }
            }
        }
    }
}

// ===========================================================================
// Flash attention on HMMA. CTA: 128 q-rows x full L sweep (128 keys/iter).
// 8 warps, warp = 16 q-rows x 128 keys. QK: split-bf16 3-pass. PV: P fp16,
// V fp16 hi/lo 2-pass. Softmax fp32 in accum layout, P never leaves regs.
// ===========================================================================
#define QST 72    // Q smem stride (bf16)
#define KST 136   // K smem stride (bf16), rows = d
#define VST 72    // V smem stride (fp16), rows = key

__global__ void __launch_bounds__(256, 1) attn_mma(
    const float* __restrict__ q, const float* __restrict__ kT,
    const float* __restrict__ v, const float* __restrict__ toep,
    float* __restrict__ x)
{
    extern __shared__ char smc[];
    uint32_t* QhU = (uint32_t*)smc;                        // 128*72 bf16
    uint32_t* QlU = QhU + 128 * QST / 2;
    uint32_t* KhU = QlU + 128 * QST / 2;                   // 64*136 bf16
    uint32_t* KlU = KhU + 64 * KST / 2;
    uint32_t* VhU = KlU + 64 * KST / 2;                    // 128*72 fp16
    uint32_t* VlU = VhU + 128 * VST / 2;
    float*    Tp  = (float*)(VlU + 128 * VST / 2);         // 4096 fp32

    const int t    = threadIdx.x;
    const int warp = t >> 5;
    const int lane = t & 31;
    const int lr   = lane >> 2;
    const int lc   = (lane & 3) * 2;
    const int qt   = blockIdx.x;
    const int h    = blockIdx.y;
    const int b    = blockIdx.z;
    const int bh   = b * HH + h;

    const float* qb = q  + (size_t)bh * LL * DD + (size_t)qt * 128 * DD;
    const float* kb = kT + (size_t)bh * DD * LL;
    const float* vb = v  + (size_t)bh * LL * DD;

    // Q tile -> bf16 hi/lo smem; toeplitz row -> smem
    #pragma unroll
    for (int ch = 0; ch < 8; ch++) {
        int fi = ch * 256 + t;
        int row = fi >> 4, dc = (fi & 15) * 4;
        float4 vv = *(const float4*)(qb + (size_t)row * 64 + dc);
        uint32_t h0 = packbf(vv.x, vv.y), h1 = packbf(vv.z, vv.w);
        float rx = vv.x - __uint_as_float(h0 << 16);
        float ry = vv.y - __uint_as_float(h0 & 0xFFFF0000u);
        float rz = vv.z - __uint_as_float(h1 << 16);
        float rw = vv.w - __uint_as_float(h1 & 0xFFFF0000u);
        int o = row * (QST / 2) + (dc >> 1);
        QhU[o] = h0; QhU[o + 1] = h1;
        QlU[o] = packbf(rx, ry); QlU[o + 1] = packbf(rz, rw);
    }
    {
        const float4* tg = (const float4*)(toep + (size_t)h * 4096);
        #pragma unroll
        for (int ch = 0; ch < 4; ch++) {
            int fi = ch * 256 + t;
            *(float4*)&Tp[fi * 4] = tg[fi];
        }
    }

    // per-thread rows (2): lr and lr+8 within warp's 16
    int qg0 = qt * 128 + warp * 16 + lr;
    int qg1 = qg0 + 8;
    const int qo0 = ((qg0 >> 5) << 6) + (qg0 & 31) + 2080;
    const int qo1 = ((qg1 >> 5) << 6) + (qg1 & 31) + 2080;

    float m0 = -1e30f, m1 = -1e30f, l0 = 0.f, l1 = 0.f;
    float O[8][4];
    #pragma unroll
    for (int nf = 0; nf < 8; nf++)
        #pragma unroll
        for (int i = 0; i < 4; i++) O[nf][i] = 0.f;

    const float scale = 0.125f;

    for (int kt = 0; kt < 8; kt++) {
        // K chunk: [64 d][128 keys] -> bf16 hi/lo
        #pragma unroll
        for (int ch = 0; ch < 8; ch++) {
            int fi = ch * 256 + t;
            int d = fi >> 5, kc = (fi & 31) * 4;
            float4 vv = *(const float4*)(kb + (size_t)d * LL + kt * 128 + kc);
            uint32_t h0 = packbf(vv.x, vv.y), h1 = packbf(vv.z, vv.w);
            float rx = vv.x - __uint_as_float(h0 << 16);
            float ry = vv.y - __uint_as_float(h0 & 0xFFFF0000u);
            float rz = vv.z - __uint_as_float(h1 << 16);
            float rw = vv.w - __uint_as_float(h1 & 0xFFFF0000u);
            int o = d * (KST / 2) + (kc >> 1);
            KhU[o] = h0; KhU[o + 1] = h1;
            KlU[o] = packbf(rx, ry); KlU[o + 1] = packbf(rz, rw);
        }
        // V chunk: [128 keys][64 d] -> fp16 hi/lo
        #pragma unroll
        for (int ch = 0; ch < 8; ch++) {
            int fi = ch * 256 + t;
            int key = fi >> 4, dc = (fi & 15) * 4;
            float4 vv = *(const float4*)(vb + (size_t)(kt * 128 + key) * 64 + dc);
            uint32_t h0 = packhf(vv.x, vv.y), h1 = packhf(vv.z, vv.w);
            __half2 hh0 = *(__half2*)&h0, hh1 = *(__half2*)&h1;
            float2 f0 = __half22float2(hh0), f1 = __half22float2(hh1);
            int o = key * (VST / 2) + (dc >> 1);
            VhU[o] = h0; VhU[o + 1] = h1;
            VlU[o] = packhf(vv.x - f0.x, vv.y - f0.y);
            VlU[o + 1] = packhf(vv.z - f1.x, vv.w - f1.y);
        }
        __syncthreads();

        // ---- S = Q K^T (split bf16, 3 passes) ----
        float S[16][4];
        #pragma unroll
        for (int nf = 0; nf < 16; nf++)
            #pragma unroll
            for (int i = 0; i < 4; i++) S[nf][i] = 0.f;

        #pragma unroll
        for (int ks = 0; ks < 4; ks++) {
            uint32_t ah[4], al[4];
            int arow = warp * 16 + (lane & 15);
            int acol = ks * 16 + ((lane >> 4) << 3);
            ldsm4(ah, s2u((const char*)QhU + (arow * QST + acol) * 2));
            ldsm4(al, s2u((const char*)QlU + (arow * QST + acol) * 2));
            int brow = ks * 16 + (lane & 15);
            int bcol = (lane >> 4) << 3;
            #pragma unroll
            for (int nf2 = 0; nf2 < 8; nf2++) {
                uint32_t bhv[4], blv[4];
                int boff = (brow * KST + nf2 * 16 + bcol) * 2;
                ldsm4t(bhv, s2u((const char*)KhU + boff));
                ldsm4t(blv, s2u((const char*)KlU + boff));
                mma_bf16(S[nf2 * 2],     ah, bhv);
                mma_bf16(S[nf2 * 2],     ah, blv);
                mma_bf16(S[nf2 * 2],     al, bhv);
                mma_bf16(S[nf2 * 2 + 1], ah, bhv + 2);
                mma_bf16(S[nf2 * 2 + 1], ah, blv + 2);
                mma_bf16(S[nf2 * 2 + 1], al, bhv + 2);
            }
        }

        // ---- scale + toeplitz bias ----
        #pragma unroll
        for (int nf = 0; nf < 16; nf++) {
            int kg0 = kt * 128 + nf * 8 + lc;
            int ko0 = ((kg0 >> 5) << 6) + (kg0 & 31);
            int kg1 = kg0 + 1;
            int ko1 = ((kg1 >> 5) << 6) + (kg1 & 31);
            S[nf][0] = S[nf][0] * scale + Tp[qo0 - ko0];
            S[nf][1] = S[nf][1] * scale + Tp[qo0 - ko1];
            S[nf][2] = S[nf][2] * scale + Tp[qo1 - ko0];
            S[nf][3] = S[nf][3] * scale + Tp[qo1 - ko1];
        }

        // ---- online softmax (rows lr, lr+8; 4 lanes share a row) ----
        float mx0 = -1e30f, mx1 = -1e30f;
        #pragma unroll
        for (int nf = 0; nf < 16; nf++) {
            mx0 = fmaxf(mx0, fmaxf(S[nf][0], S[nf][1]));
            mx1 = fmaxf(mx1, fmaxf(S[nf][2], S[nf][3]));
        }
        mx0 = fmaxf(mx0, __shfl_xor_sync(0xffffffffu, mx0, 1));
        mx0 = fmaxf(mx0, __shfl_xor_sync(0xffffffffu, mx0, 2));
        mx1 = fmaxf(mx1, __shfl_xor_sync(0xffffffffu, mx1, 1));
        mx1 = fmaxf(mx1, __shfl_xor_sync(0xffffffffu, mx1, 2));
        float nm0 = fmaxf(m0, mx0), nm1 = fmaxf(m1, mx1);
        float al0 = __expf(m0 - nm0), al1 = __expf(m1 - nm1);
        m0 = nm0; m1 = nm1;
        float sum0 = 0.f, sum1 = 0.f;
        #pragma unroll
        for (int nf = 0; nf < 16; nf++) {
            S[nf][0] = __expf(S[nf][0] - nm0);
            S[nf][1] = __expf(S[nf][1] - nm0);
            S[nf][2] = __expf(S[nf][2] - nm1);
            S[nf][3] = __expf(S[nf][3] - nm1);
            sum0 += S[nf][0] + S[nf][1];
            sum1 += S[nf][2] + S[nf][3];
        }
        sum0 += __shfl_xor_sync(0xffffffffu, sum0, 1);
        sum0 += __shfl_xor_sync(0xffffffffu, sum0, 2);
        sum1 += __shfl_xor_sync(0xffffffffu, sum1, 1);
        sum1 += __shfl_xor_sync(0xffffffffu, sum1, 2);
        l0 = l0 * al0 + sum0;
        l1 = l1 * al1 + sum1;
        #pragma unroll
        for (int nf = 0; nf < 8; nf++) {
            O[nf][0] *= al0; O[nf][1] *= al0;
            O[nf][2] *= al1; O[nf][3] *= al1;
        }

        // ---- P -> fp16 A-fragments (in regs) ----
        uint32_t ph[16][2];
        #pragma unroll
        for (int nf = 0; nf < 16; nf++) {
            ph[nf][0] = packhf(S[nf][0], S[nf][1]);
            ph[nf][1] = packhf(S[nf][2], S[nf][3]);
        }

        // ---- O += P V (fp16, V split 2 passes) ----
        #pragma unroll
        for (int ks = 0; ks < 8; ks++) {
            uint32_t pa[4] = { ph[ks * 2][0], ph[ks * 2][1],
                               ph[ks * 2 + 1][0], ph[ks * 2 + 1][1] };
            int brow = ks * 16 + (lane & 15);
            int bcol = (lane >> 4) << 3;
            #pragma unroll
            for (int nf2 = 0; nf2 < 4; nf2++) {
                uint32_t bhv[4], blv[4];
                int boff = (brow * VST + nf2 * 16 + bcol) * 2;
                ldsm4t(bhv, s2u((const char*)VhU + boff));
                ldsm4t(blv, s2u((const char*)VlU + boff));
                mma_f16(O[nf2 * 2],     pa, bhv);
                mma_f16(O[nf2 * 2],     pa, blv);
                mma_f16(O[nf2 * 2 + 1], pa, bhv + 2);
                mma_f16(O[nf2 * 2 + 1], pa, blv + 2);
            }
        }
        __syncthreads();
    }

    // ---- write out ----
    float inv0 = 1.0f / l0, inv1 = 1.0f / l1;
    int row0 = b * LL + qt * 128 + warp * 16 + lr;
    #pragma unroll
    for (int nf = 0; nf < 8; nf++) {
        int col = h * 64 + nf * 8 + lc;
        *(float2*)&x[(size_t)row0 * 512 + col] =
            make_float2(O[nf][0] * inv0, O[nf][1] * inv0);
        *(float2*)&x[(size_t)(row0 + 8) * 512 + col] =
            make_float2(O[nf][2] * inv1, O[nf][3] * inv1);
    }
}

// ===========================================================================
extern "C" void kernel_launch(void* const* d_in, const int* in_sizes, int n_in,
                              void* d_out, int out_size)
{
    const float* inq  = (const float*)d_in[0];
    const float* inkv = (const float*)d_in[1];
    const float* Wq   = (const float*)d_in[2];
    const float* bq   = (const float*)d_in[3];
    const float* Wk   = (const float*)d_in[4];
    const float* bk   = (const float*)d_in[5];
    const float* Wv   = (const float*)d_in[6];
    const float* bv   = (const float*)d_in[7];
    const float* Wo   = (const float*)d_in[8];
    const float* bo   = (const float*)d_in[9];
    const float* toep = (const float*)d_in[10];
    float* out = (float*)d_out;

    float *pq, *pkT, *pv, *px;
    cudaGetSymbolAddress((void**)&pq,  g_q);
    cudaGetSymbolAddress((void**)&pkT, g_kT);
    cudaGetSymbolAddress((void**)&pv,  g_v);
    cudaGetSymbolAddress((void**)&px,  g_x);

    dim3 gg(4, 128);

    gemm_mma<<<gg, 256>>>(inq,  Wq, bq, pq,  1);
    gemm_mma<<<gg, 256>>>(inkv, Wk, bk, pkT, 2);
    gemm_mma<<<gg, 256>>>(inkv, Wv, bv, pv,  1);

    // smem: Q 2*18432 + K 2*17408 + V 2*18432 + Tp 16384 = 124928 B
    int smem = 2 * (128 * QST * 2) + 2 * (64 * KST * 2) + 2 * (128 * VST * 2) + 4096 * 4;
    cudaFuncSetAttribute(attn_mma, cudaFuncAttributeMaxDynamicSharedMemorySize, smem);
    attn_mma<<<dim3(8, HH, BB), 256, smem>>>(pq, pkT, pv, toep, px);

    gemm_mma<<<gg, 256>>>(px, Wo, bo, out, 0);
}